// round 11
// baseline (speedup 1.0000x reference)
#include <cuda_runtime.h>
#include <cstdint>

#define N 4096
#define H 64
#define NLAYER 3
#define MAXD 128
#define NEG 0.2f
#define EPS 1e-5f

// ---------------- scratch ----------------
__device__ float g_x[N * H];          // embedding (residual)
__device__ float g_h[N * H];          // buffer A
__device__ float g_hw[N * H];         // buffer B
__device__ float g_ssrc[2][N];        // score banks (layer parity)
__device__ float g_sdst[2][N];
__device__ int   g_deg[N];            // raw in-degree (no self); reset to 0 by k_final
__device__ int   g_cols[N * MAXD];
__device__ float g_wa[4][64];         // W@asrc/W@adst for layers 1,2
__device__ float g_part[64 * 64];
__device__ int   g_cnt;               // reset by k_final

// ---------------- k_embed_edges: blocks 0-63 embed+scores+wa, blocks 64-575 edge build ----------------
__global__ void k_embed_edges(const float* __restrict__ adj,
                              const int* __restrict__ ts,
                              const float* __restrict__ arr, const float* __restrict__ dep,
                              const float* __restrict__ hard,
                              const float* __restrict__ w1, const float* __restrict__ b1,
                              const float* __restrict__ w2, const float* __restrict__ b2,
                              const float* __restrict__ gw, const float* __restrict__ gas,
                              const float* __restrict__ gad) {
    int tid = threadIdx.x;

    if (blockIdx.x >= 64) {
        // ---------- edge part: build in-neighbor lists (float4 streaming) ----------
        int gid = (blockIdx.x - 64) * 256 + tid;       // 0..131071
        int i4 = gid & (N / 4 - 1);
        int s = gid >> 10;                              // 0..127
        const int JS = 32;
        int j0 = s * JS;
        const float4* p = (const float4*)adj + (size_t)j0 * (N / 4) + i4;
        int i = i4 * 4;
        #pragma unroll 4
        for (int jj = 0; jj < JS; jj++) {
            float4 v = __ldcs(p);
            p += N / 4;
            int j = j0 + jj;
            if (v.x != 0.f && j != i) {
                int sl = atomicAdd(&g_deg[i], 1);
                if (sl < MAXD - 1) g_cols[i * MAXD + sl] = j;
            }
            if (v.y != 0.f && j != i + 1) {
                int sl = atomicAdd(&g_deg[i + 1], 1);
                if (sl < MAXD - 1) g_cols[(i + 1) * MAXD + sl] = j;
            }
            if (v.z != 0.f && j != i + 2) {
                int sl = atomicAdd(&g_deg[i + 2], 1);
                if (sl < MAXD - 1) g_cols[(i + 2) * MAXD + sl] = j;
            }
            if (v.w != 0.f && j != i + 3) {
                int sl = atomicAdd(&g_deg[i + 3], 1);
                if (sl < MAXD - 1) g_cols[(i + 3) * MAXD + sl] = j;
            }
        }
        return;
    }

    // ---------- embed part ----------
    __shared__ float sc1[64], sc2[64], sc3[64];
    __shared__ float swas[64], swad[64];
    if (tid < 64) {
        float c1 = 0.f, c2 = 0.f, c3 = 0.f;
        #pragma unroll 8
        for (int k = 0; k < 64; k++) {
            float w = w2[k * 64 + tid];
            c1 += w1[k] * w;
            c2 += w1[64 + k] * w;
            c3 += b1[k] * w;
        }
        sc1[tid] = c1; sc2[tid] = c2; sc3[tid] = c3 + b2[tid];
        // layer-0 wa vectors (block-local)
        float ws = 0.f, wd = 0.f;
        #pragma unroll 8
        for (int c = 0; c < 64; c++) {
            float w = gw[tid * 64 + c];
            ws += w * gas[c];
            wd += w * gad[c];
        }
        swas[tid] = ws; swad[tid] = wd;
    }
    if (blockIdx.x == 0 && tid >= 64 && tid < 128) {
        int k = tid - 64;
        for (int l = 1; l < 3; l++) {
            float ws = 0.f, wd = 0.f;
            #pragma unroll 8
            for (int c = 0; c < 64; c++) {
                float w = gw[l * 4096 + k * 64 + c];
                ws += w * gas[l * 64 + c];
                wd += w * gad[l * 64 + c];
            }
            g_wa[(l - 1) * 2][k] = ws;
            g_wa[(l - 1) * 2 + 1][k] = wd;
        }
    }
    __syncthreads();

    int b = *ts;
    float t = (b > -100000 && b < 100000) ? (float)b : __int_as_float(b);
    int base = blockIdx.x * 4096;
    #pragma unroll
    for (int it = 0; it < 16; it++) {
        int idx = base + it * 256 + tid;
        int i = idx >> 6, c = idx & 63;
        float p = (t - arr[i]) / (dep[i] - arr[i]);
        float v = p * sc1[c] + hard[i] * sc2[c] + sc3[c];
        g_x[idx] = v;
        g_h[idx] = v;
    }
    __syncthreads();

    // layer-0 scores (bank 0): 8 warps x 8 rows
    int w = tid >> 5, lane = tid & 31;
    int c2 = lane * 2;
    float2 vs = *(const float2*)&swas[c2];
    float2 vd = *(const float2*)&swad[c2];
    int r0 = blockIdx.x * 64 + w * 8;
    for (int rr = 0; rr < 8; rr++) {
        int row = r0 + rr;
        float2 hv = *(const float2*)&g_h[row * 64 + c2];
        float s = hv.x * vs.x + hv.y * vs.y;
        float d = hv.x * vd.x + hv.y * vd.y;
        #pragma unroll
        for (int o = 16; o; o >>= 1) {
            s += __shfl_xor_sync(0xffffffffu, s, o);
            d += __shfl_xor_sync(0xffffffffu, d, o);
        }
        if (lane == 0) { g_ssrc[0][row] = s; g_sdst[0][row] = d; }
    }
}

// ---------------- k_attn: 512 thr = 4 rows x 4 warps; no W staging; vectorized gather; named barriers ----------------
__global__ void __launch_bounds__(512) k_attn(const float* __restrict__ W,
                                              const float* __restrict__ bias, int l) {
    __shared__ int   sj[4][MAXD];
    __shared__ float swt[4][MAXD];
    __shared__ float smax[4][4];
    __shared__ float sden[4][4];
    __shared__ float sacc[4][4][64];       // phase-B unnormalized partials
    __shared__ float spart[4][4][64];      // phase-C GEMM partials

    const float* hin  = (l == 1) ? g_hw : g_h;
    float*       hout = (l == 1) ? g_h  : g_hw;
    const float* ssrc = g_ssrc[l & 1];
    const float* sdst = g_sdst[l & 1];
    float* nssrc = g_ssrc[(l + 1) & 1];
    float* nsdst = g_sdst[(l + 1) & 1];
    int last = (l == 2);

    int tid = threadIdx.x;
    int w = tid >> 5, lane = tid & 31;
    int r = w >> 2;                       // local row 0..3
    int q = w & 3;                        // quarter
    int wg = q * 32 + lane;               // 0..127
    int i = blockIdx.x * 4 + r;
    int barid = r + 1;

    int draw = g_deg[i]; if (draw > MAXD - 1) draw = MAXD - 1;
    int d = draw + 1;                     // + implicit self loop at index draw
    float sd = sdst[i];

    // ---- phase A: one logit per thread ----
    float e = -1e30f; int j = 0;
    if (wg < draw) {
        j = g_cols[i * MAXD + wg];
        e = ssrc[j] + sd;
        e = e > 0.f ? e : NEG * e;
    } else if (wg == draw) {
        j = i;
        e = ssrc[i] + sd;
        e = e > 0.f ? e : NEG * e;
    }
    float mx = e;
    #pragma unroll
    for (int o = 16; o; o >>= 1) mx = fmaxf(mx, __shfl_xor_sync(0xffffffffu, mx, o));
    if (lane == 0) smax[r][q] = mx;
    asm volatile("bar.sync %0, %1;" :: "r"(barid), "r"(128) : "memory");
    float m = fmaxf(fmaxf(smax[r][0], smax[r][1]), fmaxf(smax[r][2], smax[r][3]));

    float wgt = (wg < d) ? __expf(e - m) : 0.f;
    sj[r][wg] = j;
    swt[r][wg] = wgt;
    float den = wgt;
    #pragma unroll
    for (int o = 16; o; o >>= 1) den += __shfl_xor_sync(0xffffffffu, den, o);
    if (lane == 0) sden[r][q] = den;
    asm volatile("bar.sync %0, %1;" :: "r"(barid), "r"(128) : "memory");

    // ---- phase B: 2 neighbors per warp-iteration (16-lane subgroups, float4 loads) ----
    {
        int g = lane >> 4;                // subgroup 0/1
        int c4 = (lane & 15) * 4;         // 4 columns per lane
        float4 A = make_float4(0.f, 0.f, 0.f, 0.f);
        int nu = (d - q + 7) >> 3;        // iterations (zero-padded slots safe, t <= 127)
        int t = q + 4 * g;
        for (int u = 0; u < nu; u++, t += 8) {
            int jj = sj[r][t];
            float ww = swt[r][t];
            float4 hv = *(const float4*)&hin[jj * 64 + c4];
            A.x += ww * hv.x; A.y += ww * hv.y;
            A.z += ww * hv.z; A.w += ww * hv.w;
        }
        // combine subgroups (lane L += lane L+16)
        A.x += __shfl_xor_sync(0xffffffffu, A.x, 16);
        A.y += __shfl_xor_sync(0xffffffffu, A.y, 16);
        A.z += __shfl_xor_sync(0xffffffffu, A.z, 16);
        A.w += __shfl_xor_sync(0xffffffffu, A.w, 16);
        if (g == 0) *(float4*)&sacc[r][q][c4] = A;
    }
    asm volatile("bar.sync %0, %1;" :: "r"(barid), "r"(128) : "memory");

    // ---- phase C: k-chunked epilogue GEMM; W direct from gmem (L1-hot) ----
    const int c2 = lane * 2;
    {
        float o0 = 0.f, o1 = 0.f;
        int k0 = q * 16;
        #pragma unroll
        for (int kk = 0; kk < 16; kk++) {
            int k = k0 + kk;
            float a = sacc[r][0][k] + sacc[r][1][k] + sacc[r][2][k] + sacc[r][3][k];
            float2 wk = __ldg((const float2*)&W[k * 64 + c2]);
            o0 += a * wk.x; o1 += a * wk.y;
        }
        *(float2*)&spart[r][q][c2] = make_float2(o0, o1);
    }
    asm volatile("bar.sync %0, %1;" :: "r"(barid), "r"(128) : "memory");

    // ---- phase D: q==0 warp finalizes its row ----
    if (q == 0) {
        float denf = sden[r][0] + sden[r][1] + sden[r][2] + sden[r][3];
        float inv = 1.0f / denf;
        float2 p0 = *(const float2*)&spart[r][0][c2];
        float2 p1 = *(const float2*)&spart[r][1][c2];
        float2 p2 = *(const float2*)&spart[r][2][c2];
        float2 p3 = *(const float2*)&spart[r][3][c2];
        float2 bb = *(const float2*)&bias[c2];
        float o0 = (p0.x + p1.x + p2.x + p3.x) * inv + bb.x;
        float o1 = (p0.y + p1.y + p2.y + p3.y) * inv + bb.y;

        if (!last) {
            o0 = fmaxf(o0, 0.f); o1 = fmaxf(o1, 0.f);
            *(float2*)&hout[i * 64 + c2] = make_float2(o0, o1);
            // next-layer scores -> opposite bank
            float2 ns = *(const float2*)&g_wa[l * 2][c2];
            float2 nd = *(const float2*)&g_wa[l * 2 + 1][c2];
            float s = o0 * ns.x + o1 * ns.y;
            float dd = o0 * nd.x + o1 * nd.y;
            #pragma unroll
            for (int o = 16; o; o >>= 1) {
                s += __shfl_xor_sync(0xffffffffu, s, o);
                dd += __shfl_xor_sync(0xffffffffu, dd, o);
            }
            if (lane == 0) { nssrc[i] = s; nsdst[i] = dd; }
        } else {
            // residual + layernorm
            float2 xv = *(const float2*)&g_x[i * 64 + c2];
            float v0 = xv.x + o0, v1 = xv.y + o1;
            float s = v0 + v1;
            #pragma unroll
            for (int o = 16; o; o >>= 1) s += __shfl_xor_sync(0xffffffffu, s, o);
            float mu = s * (1.0f / 64.0f);
            float d0 = v0 - mu, d1 = v1 - mu;
            float qq = d0 * d0 + d1 * d1;
            #pragma unroll
            for (int o = 16; o; o >>= 1) qq += __shfl_xor_sync(0xffffffffu, qq, o);
            float rn = rsqrtf(qq * (1.0f / 64.0f) + EPS);
            *(float2*)&hout[i * 64 + c2] = make_float2(d0 * rn, d1 * rn);
        }
    }
}

// ---------------- k_final: pool + head + state reset for next replay ----------------
__global__ void k_final(const float* __restrict__ vw, const float* __restrict__ vb,
                        float* __restrict__ out) {
    __shared__ float sm[4][64];
    __shared__ int isLast;
    int tid = threadIdx.x;
    int c = tid & 63, g = tid >> 6;
    int rb = blockIdx.x * 64;
    float s = 0.f;
    #pragma unroll 4
    for (int r = g; r < 64; r += 4) s += g_hw[(rb + r) * 64 + c];
    sm[g][c] = s;
    __syncthreads();
    if (tid < 64) g_part[blockIdx.x * 64 + tid] = sm[0][tid] + sm[1][tid] + sm[2][tid] + sm[3][tid];
    __threadfence();
    __syncthreads();
    if (tid == 0) isLast = (atomicAdd(&g_cnt, 1) == 63);
    __syncthreads();
    if (!isLast) return;

    // last block: finish head
    float acc = 0.f;
    if (tid < 64) {
        #pragma unroll 8
        for (int b = 0; b < 64; b++) acc += g_part[b * 64 + tid];
        sm[0][tid] = acc * (1.0f / (float)N) * vw[tid];
    }
    __syncthreads();
    if (tid < 32) {
        float t = sm[0][tid] + sm[0][tid + 32];
        #pragma unroll
        for (int o = 16; o; o >>= 1) t += __shfl_xor_sync(0xffffffffu, t, o);
        if (tid == 0) {
            float r = t + vb[0];
            out[0] = r > 0.f ? r : 0.f;
        }
    }
    // reset state for the next replay (deterministic: every execution starts at 0)
    for (int k = tid; k < N; k += 256) g_deg[k] = 0;
    if (tid == 0) g_cnt = 0;
}

// ---------------- host ----------------
extern "C" void kernel_launch(void* const* d_in, const int* in_sizes, int n_in,
                              void* d_out, int out_size) {
    const float* adj      = (const float*)d_in[0];
    const int*   ts       = (const int*)  d_in[1];
    const float* arrivals = (const float*)d_in[2];
    const float* depart   = (const float*)d_in[3];
    const float* hard     = (const float*)d_in[4];
    const float* emb_w1   = (const float*)d_in[6];
    const float* emb_b1   = (const float*)d_in[7];
    const float* emb_w2   = (const float*)d_in[8];
    const float* emb_b2   = (const float*)d_in[9];
    const float* gat_w    = (const float*)d_in[10];
    const float* gat_asrc = (const float*)d_in[11];
    const float* gat_adst = (const float*)d_in[12];
    const float* gat_b    = (const float*)d_in[13];
    const float* val_w    = (const float*)d_in[14];
    const float* val_b    = (const float*)d_in[15];

    k_embed_edges<<<576, 256>>>(adj, ts, arrivals, depart, hard,
                                emb_w1, emb_b1, emb_w2, emb_b2,
                                gat_w, gat_asrc, gat_adst);

    for (int l = 0; l < NLAYER; l++)
        k_attn<<<N / 4, 512>>>(gat_w + l * H * H, gat_b + l * H, l);

    k_final<<<64, 256>>>(val_w, val_b, (float*)d_out);
}

// round 13
// speedup vs baseline: 1.0714x; 1.0714x over previous
#include <cuda_runtime.h>
#include <cstdint>

#define N 4096
#define H 64
#define NLAYER 3
#define MAXD 128
#define NEG 0.2f
#define EPS 1e-5f

// ---------------- scratch ----------------
__device__ float g_x[N * H];          // embedding (residual)
__device__ float g_h[N * H];          // buffer A
__device__ float g_hw[N * H];         // buffer B
__device__ float g_ssrc[2][N];        // score banks (layer parity)
__device__ float g_sdst[2][N];
__device__ int   g_deg[N];            // raw in-degree (no self); reset to 0 by k_final
__device__ int   g_cols[N * MAXD];
__device__ float g_wa[4][64];         // W@asrc/W@adst for layers 1,2
__device__ float g_part[64 * 64];
__device__ int   g_cnt;               // reset by k_final

// ---------------- k_embed_edges: blocks 0-63 embed+scores+wa, blocks 64-575 edge build ----------------
__global__ void k_embed_edges(const float* __restrict__ adj,
                              const int* __restrict__ ts,
                              const float* __restrict__ arr, const float* __restrict__ dep,
                              const float* __restrict__ hard,
                              const float* __restrict__ w1, const float* __restrict__ b1,
                              const float* __restrict__ w2, const float* __restrict__ b2,
                              const float* __restrict__ gw, const float* __restrict__ gas,
                              const float* __restrict__ gad) {
    int tid = threadIdx.x;

    if (blockIdx.x >= 64) {
        // ---------- edge part: build in-neighbor lists (float4 streaming) ----------
        int gid = (blockIdx.x - 64) * 256 + tid;       // 0..131071
        int i4 = gid & (N / 4 - 1);
        int s = gid >> 10;                              // 0..127
        const int JS = 32;
        int j0 = s * JS;
        const float4* p = (const float4*)adj + (size_t)j0 * (N / 4) + i4;
        int i = i4 * 4;
        #pragma unroll 4
        for (int jj = 0; jj < JS; jj++) {
            float4 v = __ldcs(p);
            p += N / 4;
            int j = j0 + jj;
            if (v.x != 0.f && j != i) {
                int sl = atomicAdd(&g_deg[i], 1);
                if (sl < MAXD - 1) g_cols[i * MAXD + sl] = j;
            }
            if (v.y != 0.f && j != i + 1) {
                int sl = atomicAdd(&g_deg[i + 1], 1);
                if (sl < MAXD - 1) g_cols[(i + 1) * MAXD + sl] = j;
            }
            if (v.z != 0.f && j != i + 2) {
                int sl = atomicAdd(&g_deg[i + 2], 1);
                if (sl < MAXD - 1) g_cols[(i + 2) * MAXD + sl] = j;
            }
            if (v.w != 0.f && j != i + 3) {
                int sl = atomicAdd(&g_deg[i + 3], 1);
                if (sl < MAXD - 1) g_cols[(i + 3) * MAXD + sl] = j;
            }
        }
        return;
    }

    // ---------- embed part ----------
    __shared__ float sc1[64], sc2[64], sc3[64];
    __shared__ float swas[64], swad[64];
    if (tid < 64) {
        float c1 = 0.f, c2 = 0.f, c3 = 0.f;
        #pragma unroll 8
        for (int k = 0; k < 64; k++) {
            float w = w2[k * 64 + tid];
            c1 += w1[k] * w;
            c2 += w1[64 + k] * w;
            c3 += b1[k] * w;
        }
        sc1[tid] = c1; sc2[tid] = c2; sc3[tid] = c3 + b2[tid];
        // layer-0 wa vectors (block-local)
        float ws = 0.f, wd = 0.f;
        #pragma unroll 8
        for (int c = 0; c < 64; c++) {
            float w = gw[tid * 64 + c];
            ws += w * gas[c];
            wd += w * gad[c];
        }
        swas[tid] = ws; swad[tid] = wd;
    }
    if (blockIdx.x == 0 && tid >= 64 && tid < 128) {
        int k = tid - 64;
        for (int l = 1; l < 3; l++) {
            float ws = 0.f, wd = 0.f;
            #pragma unroll 8
            for (int c = 0; c < 64; c++) {
                float w = gw[l * 4096 + k * 64 + c];
                ws += w * gas[l * 64 + c];
                wd += w * gad[l * 64 + c];
            }
            g_wa[(l - 1) * 2][k] = ws;
            g_wa[(l - 1) * 2 + 1][k] = wd;
        }
    }
    __syncthreads();

    int b = *ts;
    float t = (b > -100000 && b < 100000) ? (float)b : __int_as_float(b);
    int base = blockIdx.x * 4096;
    #pragma unroll
    for (int it = 0; it < 16; it++) {
        int idx = base + it * 256 + tid;
        int i = idx >> 6, c = idx & 63;
        float p = (t - arr[i]) / (dep[i] - arr[i]);
        float v = p * sc1[c] + hard[i] * sc2[c] + sc3[c];
        g_x[idx] = v;
        g_h[idx] = v;
    }
    __syncthreads();

    // layer-0 scores (bank 0): 8 warps x 8 rows
    int w = tid >> 5, lane = tid & 31;
    int c2 = lane * 2;
    float2 vs = *(const float2*)&swas[c2];
    float2 vd = *(const float2*)&swad[c2];
    int r0 = blockIdx.x * 64 + w * 8;
    for (int rr = 0; rr < 8; rr++) {
        int row = r0 + rr;
        float2 hv = *(const float2*)&g_h[row * 64 + c2];
        float s = hv.x * vs.x + hv.y * vs.y;
        float d = hv.x * vd.x + hv.y * vd.y;
        #pragma unroll
        for (int o = 16; o; o >>= 1) {
            s += __shfl_xor_sync(0xffffffffu, s, o);
            d += __shfl_xor_sync(0xffffffffu, d, o);
        }
        if (lane == 0) { g_ssrc[0][row] = s; g_sdst[0][row] = d; }
    }
}

// ---------------- k_attn: 512 thr = 4 rows x 4 warps; global-max softmax; batched gather ----------------
__global__ void __launch_bounds__(512) k_attn(const float* __restrict__ W,
                                              const float* __restrict__ bias, int l) {
    __shared__ int   sj[4][MAXD];
    __shared__ float swt[4][MAXD];          // exp(e - m_global): any warp may read any slot
    __shared__ float smax[4][4];
    __shared__ float sden[4][4];
    __shared__ float sacc[4][4][64];        // phase-B partials
    __shared__ float spart[4][4][64];       // phase-C GEMM partials

    const float* hin  = (l == 1) ? g_hw : g_h;
    float*       hout = (l == 1) ? g_h  : g_hw;
    const float* ssrc = g_ssrc[l & 1];
    const float* sdst = g_sdst[l & 1];
    float* nssrc = g_ssrc[(l + 1) & 1];
    float* nsdst = g_sdst[(l + 1) & 1];
    int last = (l == 2);

    int tid = threadIdx.x;
    int w = tid >> 5, lane = tid & 31;
    int r = w >> 2;                       // local row 0..3
    int q = w & 3;                        // quarter
    int wg = q * 32 + lane;               // 0..127
    int i = blockIdx.x * 4 + r;
    int barid = r + 1;

    int draw = g_deg[i]; if (draw > MAXD - 1) draw = MAXD - 1;
    int d = draw + 1;                     // + implicit self loop at index draw
    float sd = sdst[i];

    // ---- phase A: logits + GLOBAL max (2 barriers; provably exact) ----
    float e = -1e30f; int j = 0;
    if (wg < draw) {
        j = g_cols[i * MAXD + wg];
        e = ssrc[j] + sd;
        e = e > 0.f ? e : NEG * e;
    } else if (wg == draw) {
        j = i;
        e = ssrc[i] + sd;
        e = e > 0.f ? e : NEG * e;
    }
    float mxq = e;
    #pragma unroll
    for (int o = 16; o; o >>= 1) mxq = fmaxf(mxq, __shfl_xor_sync(0xffffffffu, mxq, o));
    if (lane == 0) smax[r][q] = mxq;
    asm volatile("bar.sync %0, %1;" :: "r"(barid), "r"(128) : "memory");
    float m = fmaxf(fmaxf(smax[r][0], smax[r][1]), fmaxf(smax[r][2], smax[r][3]));

    float wgt = (wg < d) ? __expf(e - m) : 0.f;
    sj[r][wg] = j;
    swt[r][wg] = wgt;
    float den = wgt;
    #pragma unroll
    for (int o = 16; o; o >>= 1) den += __shfl_xor_sync(0xffffffffu, den, o);
    if (lane == 0) sden[r][q] = den;
    asm volatile("bar.sync %0, %1;" :: "r"(barid), "r"(128) : "memory");

    // ---- phase B: batched branch-free gather (16-lane subgroups, float4, MLP=6) ----
    {
        int g = lane >> 4;                // subgroup 0/1
        int c4 = (lane & 15) * 4;         // 4 columns per lane
        float4 A = make_float4(0.f, 0.f, 0.f, 0.f);
        // all 128 slots valid (wgt=0 beyond d) -> fixed unroll, no predication
        int jv[6]; float wv[6];
        #pragma unroll
        for (int u = 0; u < 6; u++) {
            int t = q + 4 * g + 8 * u;    // <= 47
            jv[u] = sj[r][t];
            wv[u] = swt[r][t];
        }
        #pragma unroll
        for (int u = 0; u < 6; u++) {
            float4 hv = *(const float4*)&hin[jv[u] * 64 + c4];
            A.x += wv[u] * hv.x; A.y += wv[u] * hv.y;
            A.z += wv[u] * hv.z; A.w += wv[u] * hv.w;
        }
        // rare tail: d > 48
        for (int t = 48 + q + 4 * g; t < d; t += 8) {
            int jj = sj[r][t];
            float ww = swt[r][t];
            float4 hv = *(const float4*)&hin[jj * 64 + c4];
            A.x += ww * hv.x; A.y += ww * hv.y;
            A.z += ww * hv.z; A.w += ww * hv.w;
        }
        // combine subgroups (lane L += lane L+16)
        A.x += __shfl_xor_sync(0xffffffffu, A.x, 16);
        A.y += __shfl_xor_sync(0xffffffffu, A.y, 16);
        A.z += __shfl_xor_sync(0xffffffffu, A.z, 16);
        A.w += __shfl_xor_sync(0xffffffffu, A.w, 16);
        if (g == 0) *(float4*)&sacc[r][q][c4] = A;
    }
    asm volatile("bar.sync %0, %1;" :: "r"(barid), "r"(128) : "memory");

    // ---- phase C: epilogue GEMM, k-chunk per warp; cooperative a[k] + shfl broadcast ----
    const int c2 = lane * 2;
    int k0 = q * 16;
    {
        int kl = k0 + (lane & 15);
        float aval = sacc[r][0][kl] + sacc[r][1][kl] + sacc[r][2][kl] + sacc[r][3][kl];
        float o0 = 0.f, o1 = 0.f;
        #pragma unroll
        for (int kk = 0; kk < 16; kk++) {
            float a = __shfl_sync(0xffffffffu, aval, kk);
            float2 wk = __ldg((const float2*)&W[(k0 + kk) * 64 + c2]);
            o0 += a * wk.x; o1 += a * wk.y;
        }
        *(float2*)&spart[r][q][c2] = make_float2(o0, o1);
    }
    asm volatile("bar.sync %0, %1;" :: "r"(barid), "r"(128) : "memory");

    // ---- phase D: q==0 warp finalizes its row ----
    if (q == 0) {
        float denf = sden[r][0] + sden[r][1] + sden[r][2] + sden[r][3];
        float inv = 1.0f / denf;
        float2 p0 = *(const float2*)&spart[r][0][c2];
        float2 p1 = *(const float2*)&spart[r][1][c2];
        float2 p2 = *(const float2*)&spart[r][2][c2];
        float2 p3 = *(const float2*)&spart[r][3][c2];
        float2 bb = *(const float2*)&bias[c2];
        float o0 = (p0.x + p1.x + p2.x + p3.x) * inv + bb.x;
        float o1 = (p0.y + p1.y + p2.y + p3.y) * inv + bb.y;

        if (!last) {
            o0 = fmaxf(o0, 0.f); o1 = fmaxf(o1, 0.f);
            *(float2*)&hout[i * 64 + c2] = make_float2(o0, o1);
            // next-layer scores -> opposite bank
            float2 ns = *(const float2*)&g_wa[l * 2][c2];
            float2 nd = *(const float2*)&g_wa[l * 2 + 1][c2];
            float s = o0 * ns.x + o1 * ns.y;
            float dd = o0 * nd.x + o1 * nd.y;
            #pragma unroll
            for (int o = 16; o; o >>= 1) {
                s += __shfl_xor_sync(0xffffffffu, s, o);
                dd += __shfl_xor_sync(0xffffffffu, dd, o);
            }
            if (lane == 0) { nssrc[i] = s; nsdst[i] = dd; }
        } else {
            // residual + layernorm
            float2 xv = *(const float2*)&g_x[i * 64 + c2];
            float v0 = xv.x + o0, v1 = xv.y + o1;
            float s = v0 + v1;
            #pragma unroll
            for (int o = 16; o; o >>= 1) s += __shfl_xor_sync(0xffffffffu, s, o);
            float mu = s * (1.0f / 64.0f);
            float d0 = v0 - mu, d1 = v1 - mu;
            float qq = d0 * d0 + d1 * d1;
            #pragma unroll
            for (int o = 16; o; o >>= 1) qq += __shfl_xor_sync(0xffffffffu, qq, o);
            float rn = rsqrtf(qq * (1.0f / 64.0f) + EPS);
            *(float2*)&hout[i * 64 + c2] = make_float2(d0 * rn, d1 * rn);
        }
    }
}

// ---------------- k_final: pool + head + state reset for next replay ----------------
__global__ void k_final(const float* __restrict__ vw, const float* __restrict__ vb,
                        float* __restrict__ out) {
    __shared__ float sm[4][64];
    __shared__ int isLast;
    int tid = threadIdx.x;
    int c = tid & 63, g = tid >> 6;
    int rb = blockIdx.x * 64;
    float s = 0.f;
    #pragma unroll 4
    for (int r = g; r < 64; r += 4) s += g_hw[(rb + r) * 64 + c];
    sm[g][c] = s;
    __syncthreads();
    if (tid < 64) g_part[blockIdx.x * 64 + tid] = sm[0][tid] + sm[1][tid] + sm[2][tid] + sm[3][tid];
    __threadfence();
    __syncthreads();
    if (tid == 0) isLast = (atomicAdd(&g_cnt, 1) == 63);
    __syncthreads();
    if (!isLast) return;

    // last block: finish head
    float acc = 0.f;
    if (tid < 64) {
        #pragma unroll 8
        for (int b = 0; b < 64; b++) acc += g_part[b * 64 + tid];
        sm[0][tid] = acc * (1.0f / (float)N) * vw[tid];
    }
    __syncthreads();
    if (tid < 32) {
        float t = sm[0][tid] + sm[0][tid + 32];
        #pragma unroll
        for (int o = 16; o; o >>= 1) t += __shfl_xor_sync(0xffffffffu, t, o);
        if (tid == 0) {
            float r = t + vb[0];
            out[0] = r > 0.f ? r : 0.f;
        }
    }
    // reset state for the next replay (deterministic: every execution starts at 0)
    for (int k = tid; k < N; k += 256) g_deg[k] = 0;
    if (tid == 0) g_cnt = 0;
}

// ---------------- host ----------------
extern "C" void kernel_launch(void* const* d_in, const int* in_sizes, int n_in,
                              void* d_out, int out_size) {
    const float* adj      = (const float*)d_in[0];
    const int*   ts       = (const int*)  d_in[1];
    const float* arrivals = (const float*)d_in[2];
    const float* depart   = (const float*)d_in[3];
    const float* hard     = (const float*)d_in[4];
    const float* emb_w1   = (const float*)d_in[6];
    const float* emb_b1   = (const float*)d_in[7];
    const float* emb_w2   = (const float*)d_in[8];
    const float* emb_b2   = (const float*)d_in[9];
    const float* gat_w    = (const float*)d_in[10];
    const float* gat_asrc = (const float*)d_in[11];
    const float* gat_adst = (const float*)d_in[12];
    const float* gat_b    = (const float*)d_in[13];
    const float* val_w    = (const float*)d_in[14];
    const float* val_b    = (const float*)d_in[15];

    k_embed_edges<<<576, 256>>>(adj, ts, arrivals, depart, hard,
                                emb_w1, emb_b1, emb_w2, emb_b2,
                                gat_w, gat_asrc, gat_adst);

    for (int l = 0; l < NLAYER; l++)
        k_attn<<<N / 4, 512>>>(gat_w + l * H * H, gat_b + l * H, l);

    k_final<<<64, 256>>>(val_w, val_b, (float*)d_out);
}